// round 1
// baseline (speedup 1.0000x reference)
#include <cuda_runtime.h>
#include <cuda_bf16.h>
#include <math.h>

// Problem constants
#define BB 8
#define CC 192
#define HH 128
#define WW 128
#define HWSZ 16384          // H*W
#define HEADS 8
#define DH 24               // C / HEADS
#define HID 384
#define NPIX (BB * HWSZ)    // 131072
#define NTOT (BB * CC * HWSZ)       // 25,165,824
#define NHID (BB * HID * HWSZ)      // 50,331,648
#define NSPLIT 16
#define GRAM_TK 128

// ---------------- scratch (device globals; no allocations allowed) -------------
__device__ float g_xn[NTOT];
__device__ float g_xm[NTOT];
__device__ float g_q[NTOT];
__device__ float g_k[NTOT];
__device__ float g_v[NTOT];
__device__ float g_oat[NTOT];
__device__ float g_fused[NTOT];
__device__ float g_xln[NTOT];
__device__ float g_hmid[NHID];
__device__ float g_attn[BB * HEADS * DH * DH];              // 36864
__device__ float g_part[NSPLIT * BB * HEADS * DH * DH];     // 589,824
__device__ float g_norms[2 * BB * CC];                      // q norms then k norms

// ---------------- channel LayerNorm (over C per pixel), optional mask ----------
__global__ void ln_kernel(const float* __restrict__ x,
                          const float* __restrict__ mask,
                          const float* __restrict__ w,
                          const float* __restrict__ bvec,
                          float* __restrict__ out_xn,
                          float* __restrict__ out_xm)
{
    int p = blockIdx.x * blockDim.x + threadIdx.x;   // global pixel
    int b = p >> 14;
    int s = p & (HWSZ - 1);
    const float* xp = x + (size_t)b * CC * HWSZ + s;

    float sum = 0.f, sq = 0.f;
#pragma unroll 8
    for (int c = 0; c < CC; c++) {
        float v = xp[(size_t)c * HWSZ];
        sum += v; sq += v * v;
    }
    float mu  = sum * (1.0f / CC);
    float var = sq * (1.0f / CC) - mu * mu;
    float inv = rsqrtf(var + 1e-5f);

    size_t base = (size_t)b * CC * HWSZ + s;
#pragma unroll 4
    for (int c = 0; c < CC; c++) {
        size_t off = base + (size_t)c * HWSZ;
        float v = (x[off] - mu) * inv * w[c] + bvec[c];
        out_xn[off] = v;
        if (mask) out_xm[off] = v * fmaxf(mask[off], 0.1f);
    }
}

// ---------------- tiled SGEMM: C[bz, M, HW] = A[M,K] @ B[bz, K, HW] ------------
// BM=BN=64, BK=16, 256 threads, 4x4 per thread. Optional bias[M], residual
// (same layout as C), GELU (exact, erff).
template<bool GELU>
__global__ void sgemm_kernel(const float* __restrict__ A,
                             const float* __restrict__ Bmat,
                             float* __restrict__ Cmat,
                             const float* __restrict__ bias,
                             const float* __restrict__ resid,
                             int M, int K)
{
    const int bx = blockIdx.x, by = blockIdx.y, bz = blockIdx.z;
    const int tid = threadIdx.x;

    __shared__ float As[16][64];
    __shared__ float Bs[16][64];

    const size_t bbase = (size_t)bz * K * HWSZ + (size_t)bx * 64;
    const size_t cbase = (size_t)bz * M * HWSZ + (size_t)bx * 64;

    const int arow = tid >> 2;          // 0..63
    const int acol = (tid & 3) * 4;     // 0,4,8,12
    const int brow = tid >> 4;          // 0..15
    const int bcol = (tid & 15) * 4;    // 0..60
    const int tx = tid & 15, ty = tid >> 4;

    float acc[4][4] = {};

    for (int k0 = 0; k0 < K; k0 += 16) {
        float4 av = *(const float4*)(A + (size_t)(by * 64 + arow) * K + k0 + acol);
        As[acol + 0][arow] = av.x;
        As[acol + 1][arow] = av.y;
        As[acol + 2][arow] = av.z;
        As[acol + 3][arow] = av.w;
        float4 bv = *(const float4*)(Bmat + bbase + (size_t)(k0 + brow) * HWSZ + bcol);
        *(float4*)&Bs[brow][bcol] = bv;
        __syncthreads();
#pragma unroll
        for (int kk = 0; kk < 16; kk++) {
            float4 a = *(const float4*)&As[kk][ty * 4];
            float4 b = *(const float4*)&Bs[kk][tx * 4];
            float ar[4] = {a.x, a.y, a.z, a.w};
            float br[4] = {b.x, b.y, b.z, b.w};
#pragma unroll
            for (int i = 0; i < 4; i++)
#pragma unroll
                for (int j = 0; j < 4; j++)
                    acc[i][j] = fmaf(ar[i], br[j], acc[i][j]);
        }
        __syncthreads();
    }

#pragma unroll
    for (int i = 0; i < 4; i++) {
        int row = by * 64 + ty * 4 + i;
        float bi = bias ? bias[row] : 0.f;
#pragma unroll
        for (int j = 0; j < 4; j++) {
            size_t off = cbase + (size_t)row * HWSZ + tx * 4 + j;
            float v = acc[i][j] + bi;
            if (resid) v += resid[off];
            if (GELU)  v = 0.5f * v * (1.f + erff(v * 0.70710678118f));
            Cmat[off] = v;
        }
    }
}

// ---------------- per-row L2 norms of q and k (rows = (b,c), length HW) --------
__global__ void rownorm_kernel(const float* __restrict__ q,
                               const float* __restrict__ k,
                               float* __restrict__ norms)
{
    int row = blockIdx.x;                    // 0 .. B*C-1
    const float* src = (blockIdx.y ? k : q) + (size_t)row * HWSZ;
    float s = 0.f;
    for (int i = threadIdx.x; i < HWSZ; i += 256) {
        float v = src[i];
        s = fmaf(v, v, s);
    }
#pragma unroll
    for (int off = 16; off > 0; off >>= 1)
        s += __shfl_xor_sync(0xffffffffu, s, off);
    __shared__ float sm[8];
    int lane = threadIdx.x & 31, wid = threadIdx.x >> 5;
    if (lane == 0) sm[wid] = s;
    __syncthreads();
    if (threadIdx.x < 8) {
        s = sm[threadIdx.x];
#pragma unroll
        for (int off = 4; off > 0; off >>= 1)
            s += __shfl_xor_sync(0xffu, s, off);
        if (threadIdx.x == 0)
            norms[blockIdx.y * (BB * CC) + row] = sqrtf(s);
    }
}

// ---------------- gram: part[ks, bh, c, d] = sum_{n in split} q[c,n]k[d,n] -----
// 192 threads: thread t handles d = t%24 and c in {t/24, t/24+8, t/24+16}
__global__ void gram_kernel(const float* __restrict__ q,
                            const float* __restrict__ k,
                            float* __restrict__ part)
{
    __shared__ float qs[24 * 129];
    __shared__ float ksm[24 * 129];

    int bh = blockIdx.x;           // 0..63
    int ks = blockIdx.y;           // 0..15
    int b = bh >> 3, h = bh & 7;
    const float* qb = q + (size_t)b * CC * HWSZ + (size_t)(h * DH) * HWSZ;
    const float* kb = k + (size_t)b * CC * HWSZ + (size_t)(h * DH) * HWSZ;

    int tid = threadIdx.x;
    int d  = tid % 24;
    int c0 = tid / 24;             // 0..7

    float a0 = 0.f, a1 = 0.f, a2 = 0.f;
    int kstart = ks * (HWSZ / NSPLIT);     // 1024 per split

    for (int kc = kstart; kc < kstart + (HWSZ / NSPLIT); kc += GRAM_TK) {
#pragma unroll
        for (int i = tid; i < 24 * GRAM_TK; i += 192) {
            int r = i / GRAM_TK, cl = i % GRAM_TK;
            qs[r * 129 + cl]  = qb[(size_t)r * HWSZ + kc + cl];
            ksm[r * 129 + cl] = kb[(size_t)r * HWSZ + kc + cl];
        }
        __syncthreads();
#pragma unroll 4
        for (int j = 0; j < GRAM_TK; j++) {
            float kv = ksm[d * 129 + j];
            a0 = fmaf(qs[c0 * 129 + j],        kv, a0);
            a1 = fmaf(qs[(c0 + 8) * 129 + j],  kv, a1);
            a2 = fmaf(qs[(c0 + 16) * 129 + j], kv, a2);
        }
        __syncthreads();
    }
    float* p = part + ((size_t)ks * 64 + bh) * 576;
    p[c0 * 24 + d]        = a0;
    p[(c0 + 8) * 24 + d]  = a1;
    p[(c0 + 16) * 24 + d] = a2;
}

// ---------------- reduce partials, scale by temp/(|q||k|), softmax over d ------
__global__ void softmax_kernel(const float* __restrict__ temp,
                               const float* __restrict__ part,
                               const float* __restrict__ norms,
                               float* __restrict__ attn)
{
    int bh = blockIdx.x;
    int b = bh >> 3, h = bh & 7;
    int r = threadIdx.x;
    if (r >= 24) return;
    float t = temp[h];
    float nq = fmaxf(norms[b * CC + h * DH + r], 1e-12f);
    float l[24];
    float mx = -1e30f;
#pragma unroll
    for (int d = 0; d < 24; d++) {
        float s = 0.f;
        for (int ksp = 0; ksp < NSPLIT; ksp++)
            s += part[((size_t)ksp * 64 + bh) * 576 + r * 24 + d];
        float nk = fmaxf(norms[BB * CC + b * CC + h * DH + d], 1e-12f);
        s = s * t / (nq * nk);
        l[d] = s;
        mx = fmaxf(mx, s);
    }
    float sum = 0.f;
#pragma unroll
    for (int d = 0; d < 24; d++) { l[d] = expf(l[d] - mx); sum += l[d]; }
    float inv = 1.f / sum;
#pragma unroll
    for (int d = 0; d < 24; d++)
        attn[(size_t)bh * 576 + r * 24 + d] = l[d] * inv;
}

// ---------------- out[c,n] = sum_d attn[c,d] v[d,n] (per (b,h)) ----------------
__global__ void av_kernel(const float* __restrict__ attn,
                          const float* __restrict__ v,
                          float* __restrict__ out)
{
    __shared__ float at[576];
    int bh = blockIdx.y;
    int b = bh >> 3, h = bh & 7;
    int tid = threadIdx.x;
    for (int i = tid; i < 576; i += 256) at[i] = attn[(size_t)bh * 576 + i];
    __syncthreads();

    int n = blockIdx.x * 256 + tid;
    size_t base = (size_t)b * CC * HWSZ + (size_t)(h * DH) * HWSZ + n;
    float vv[24];
#pragma unroll
    for (int d = 0; d < 24; d++) vv[d] = v[base + (size_t)d * HWSZ];
#pragma unroll
    for (int c = 0; c < 24; c++) {
        float s = 0.f;
#pragma unroll
        for (int d = 0; d < 24; d++) s = fmaf(at[c * 24 + d], vv[d], s);
        out[base + (size_t)c * HWSZ] = s;
    }
}

// ------------------------------- launcher --------------------------------------
extern "C" void kernel_launch(void* const* d_in, const int* in_sizes, int n_in,
                              void* d_out, int out_size)
{
    const float* image = (const float*)d_in[0];
    const float* mask  = (const float*)d_in[1];
    const float* n1w   = (const float*)d_in[2];
    const float* n1b   = (const float*)d_in[3];
    const float* Wq    = (const float*)d_in[4];
    const float* Wk    = (const float*)d_in[5];
    const float* Wv    = (const float*)d_in[6];
    const float* Wo    = (const float*)d_in[7];
    const float* temp  = (const float*)d_in[8];
    const float* n2w   = (const float*)d_in[9];
    const float* n2b   = (const float*)d_in[10];
    const float* fc1w  = (const float*)d_in[11];
    const float* fc1b  = (const float*)d_in[12];
    const float* fc2w  = (const float*)d_in[13];
    const float* fc2b  = (const float*)d_in[14];
    float* out = (float*)d_out;

    float *xn, *xm, *q, *k, *v, *oat, *fused, *xln, *hmid, *attn, *part, *norms;
    cudaGetSymbolAddress((void**)&xn,    g_xn);
    cudaGetSymbolAddress((void**)&xm,    g_xm);
    cudaGetSymbolAddress((void**)&q,     g_q);
    cudaGetSymbolAddress((void**)&k,     g_k);
    cudaGetSymbolAddress((void**)&v,     g_v);
    cudaGetSymbolAddress((void**)&oat,   g_oat);
    cudaGetSymbolAddress((void**)&fused, g_fused);
    cudaGetSymbolAddress((void**)&xln,   g_xln);
    cudaGetSymbolAddress((void**)&hmid,  g_hmid);
    cudaGetSymbolAddress((void**)&attn,  g_attn);
    cudaGetSymbolAddress((void**)&part,  g_part);
    cudaGetSymbolAddress((void**)&norms, g_norms);

    dim3 g192(HWSZ / 64, CC / 64, BB);     // (256, 3, 8)
    dim3 g384(HWSZ / 64, HID / 64, BB);    // (256, 6, 8)

    // 1) LN1 + clamped mask
    ln_kernel<<<NPIX / 256, 256>>>(image, mask, n1w, n1b, xn, xm);
    // 2-4) Q, K, V projections
    sgemm_kernel<false><<<g192, 256>>>(Wq, xm, q, nullptr, nullptr, CC, CC);
    sgemm_kernel<false><<<g192, 256>>>(Wk, xn, k, nullptr, nullptr, CC, CC);
    sgemm_kernel<false><<<g192, 256>>>(Wv, xn, v, nullptr, nullptr, CC, CC);
    // 5) row L2 norms of q and k
    rownorm_kernel<<<dim3(BB * CC, 2), 256>>>(q, k, norms);
    // 6) split-K gram matrices (deterministic partials)
    gram_kernel<<<dim3(64, NSPLIT), 192>>>(q, k, part);
    // 7) reduce + scale + softmax
    softmax_kernel<<<64, 32>>>(temp, part, norms, attn);
    // 8) attn @ v
    av_kernel<<<dim3(HWSZ / 256, 64), 256>>>(attn, v, oat);
    // 9) Wo projection + image residual
    sgemm_kernel<false><<<g192, 256>>>(Wo, oat, fused, nullptr, image, CC, CC);
    // 10) LN2
    ln_kernel<<<NPIX / 256, 256>>>(fused, nullptr, n2w, n2b, xln, nullptr);
    // 11) fc1 + bias + exact GELU
    sgemm_kernel<true><<<g384, 256>>>(fc1w, xln, hmid, fc1b, nullptr, HID, CC);
    // 12) fc2 + bias + fused residual -> output
    sgemm_kernel<false><<<g192, 256>>>(fc2w, hmid, out, fc2b, fused, CC, HID);
}

// round 2
// speedup vs baseline: 1.1896x; 1.1896x over previous
#include <cuda_runtime.h>
#include <cuda_bf16.h>
#include <math.h>

// Problem constants
#define BB 8
#define CC 192
#define HWSZ 16384
#define HEADS 8
#define DH 24
#define HID 384
#define NPIX (BB * HWSZ)
#define NTOT (BB * CC * HWSZ)
#define NHID (BB * HID * HWSZ)
#define NSPLIT 16
#define GRAM_TK 128

// ---------------- scratch (device globals; no allocations allowed) -------------
__device__ float g_xn[NTOT];
__device__ float g_xm[NTOT];
__device__ float g_q[NTOT];
__device__ float g_k[NTOT];
__device__ float g_v[NTOT];
__device__ float g_oat[NTOT];
__device__ float g_fused[NTOT];
__device__ float g_xln[NTOT];
__device__ float g_hmid[NHID];
__device__ float g_attn[BB * HEADS * DH * DH];
__device__ float g_part[NSPLIT * BB * HEADS * DH * DH];
__device__ float g_norms[2 * BB * CC];

// ---------------- channel LayerNorm (over C per pixel), optional mask ----------
__global__ void ln_kernel(const float* __restrict__ x,
                          const float* __restrict__ mask,
                          const float* __restrict__ w,
                          const float* __restrict__ bvec,
                          float* __restrict__ out_xn,
                          float* __restrict__ out_xm)
{
    int p = blockIdx.x * blockDim.x + threadIdx.x;
    int b = p >> 14;
    int s = p & (HWSZ - 1);
    const float* xp = x + (size_t)b * CC * HWSZ + s;

    float sum = 0.f, sq = 0.f;
#pragma unroll 8
    for (int c = 0; c < CC; c++) {
        float v = xp[(size_t)c * HWSZ];
        sum += v; sq += v * v;
    }
    float mu  = sum * (1.0f / CC);
    float var = sq * (1.0f / CC) - mu * mu;
    float inv = rsqrtf(var + 1e-5f);

    size_t base = (size_t)b * CC * HWSZ + s;
#pragma unroll 4
    for (int c = 0; c < CC; c++) {
        size_t off = base + (size_t)c * HWSZ;
        float v = (x[off] - mu) * inv * w[c] + bvec[c];
        out_xn[off] = v;
        if (mask) out_xm[off] = v * fmaxf(mask[off], 0.1f);
    }
}

// ---------------- SGEMM: C[bz, M, HW] = A[M,K] @ B[bz, K, HW] ------------------
// BM=64, BN=128, BK=16, 128 threads, 8x8 microtile, double-buffered smem.
template<bool GELU>
__global__ void __launch_bounds__(128)
sgemm_kernel(const float* __restrict__ A,
             const float* __restrict__ Bmat,
             float* __restrict__ Cmat,
             const float* __restrict__ bias,
             const float* __restrict__ resid,
             int M, int K)
{
    const int bx = blockIdx.x, by = blockIdx.y, bz = blockIdx.z;
    const int tid = threadIdx.x;

    __shared__ float As[2][16][64];
    __shared__ float Bs[2][16][128];

    const size_t bbase = (size_t)bz * K * HWSZ + (size_t)bx * 128;
    const size_t cbase = (size_t)bz * M * HWSZ + (size_t)bx * 128;

    // A tile loaders: 64x16 floats = 256 float4; 2 per thread
    const int a_row0 = tid >> 1;              // 0..63
    const int a_c4_0 = (tid & 1) * 2;         // 0 or 2  (float4 index 0..3)
    // B tile loaders: 16x128 floats = 512 float4; 4 per thread
    const int tx = tid & 15, ty = tid >> 4;   // compute layout 16x8

    const float* Aptr = A + (size_t)(by * 64 + a_row0) * K;

    float acc[8][8] = {};
    float4 areg[2], breg[4];

    // prologue: load tile 0 into buffer 0
    {
#pragma unroll
        for (int i = 0; i < 2; i++) {
            float4 av = *(const float4*)(Aptr + (a_c4_0 + i) * 4);
            As[0][(a_c4_0 + i) * 4 + 0][a_row0] = av.x;
            As[0][(a_c4_0 + i) * 4 + 1][a_row0] = av.y;
            As[0][(a_c4_0 + i) * 4 + 2][a_row0] = av.z;
            As[0][(a_c4_0 + i) * 4 + 3][a_row0] = av.w;
        }
#pragma unroll
        for (int i = 0; i < 4; i++) {
            int idx = tid + i * 128;
            int r = idx >> 5, c4 = idx & 31;
            *(float4*)&Bs[0][r][c4 * 4] =
                *(const float4*)(Bmat + bbase + (size_t)r * HWSZ + c4 * 4);
        }
    }
    __syncthreads();

    const int nt = K / 16;
    int buf = 0;
    for (int kt = 0; kt < nt; kt++) {
        // prefetch next tile into registers (overlaps with compute below)
        if (kt + 1 < nt) {
            int k0 = (kt + 1) * 16;
#pragma unroll
            for (int i = 0; i < 2; i++)
                areg[i] = *(const float4*)(Aptr + k0 + (a_c4_0 + i) * 4);
#pragma unroll
            for (int i = 0; i < 4; i++) {
                int idx = tid + i * 128;
                int r = idx >> 5, c4 = idx & 31;
                breg[i] = *(const float4*)(Bmat + bbase + (size_t)(k0 + r) * HWSZ + c4 * 4);
            }
        }

        // compute from current buffer
#pragma unroll
        for (int kk = 0; kk < 16; kk++) {
            float4 a0 = *(const float4*)&As[buf][kk][ty * 8];
            float4 a1 = *(const float4*)&As[buf][kk][ty * 8 + 4];
            float4 b0 = *(const float4*)&Bs[buf][kk][tx * 8];
            float4 b1 = *(const float4*)&Bs[buf][kk][tx * 8 + 4];
            float ar[8] = {a0.x, a0.y, a0.z, a0.w, a1.x, a1.y, a1.z, a1.w};
            float br[8] = {b0.x, b0.y, b0.z, b0.w, b1.x, b1.y, b1.z, b1.w};
#pragma unroll
            for (int i = 0; i < 8; i++)
#pragma unroll
                for (int j = 0; j < 8; j++)
                    acc[i][j] = fmaf(ar[i], br[j], acc[i][j]);
        }

        if (kt + 1 < nt) {
            int nb = buf ^ 1;
#pragma unroll
            for (int i = 0; i < 2; i++) {
                As[nb][(a_c4_0 + i) * 4 + 0][a_row0] = areg[i].x;
                As[nb][(a_c4_0 + i) * 4 + 1][a_row0] = areg[i].y;
                As[nb][(a_c4_0 + i) * 4 + 2][a_row0] = areg[i].z;
                As[nb][(a_c4_0 + i) * 4 + 3][a_row0] = areg[i].w;
            }
#pragma unroll
            for (int i = 0; i < 4; i++) {
                int idx = tid + i * 128;
                int r = idx >> 5, c4 = idx & 31;
                *(float4*)&Bs[nb][r][c4 * 4] = breg[i];
            }
            __syncthreads();
            buf = nb;
        }
    }

    // epilogue
#pragma unroll
    for (int i = 0; i < 8; i++) {
        int row = by * 64 + ty * 8 + i;
        float bi = bias ? bias[row] : 0.f;
        size_t rowoff = cbase + (size_t)row * HWSZ + tx * 8;
        float vout[8];
#pragma unroll
        for (int j = 0; j < 8; j++) {
            float v = acc[i][j] + bi;
            if (resid) v += resid[rowoff + j];
            if (GELU)  v = 0.5f * v * (1.f + erff(v * 0.70710678118f));
            vout[j] = v;
        }
        *(float4*)(Cmat + rowoff)     = make_float4(vout[0], vout[1], vout[2], vout[3]);
        *(float4*)(Cmat + rowoff + 4) = make_float4(vout[4], vout[5], vout[6], vout[7]);
    }
}

// ---------------- per-row L2 norms of q and k ----------------------------------
__global__ void rownorm_kernel(const float* __restrict__ q,
                               const float* __restrict__ k,
                               float* __restrict__ norms)
{
    int row = blockIdx.x;
    const float* src = (blockIdx.y ? k : q) + (size_t)row * HWSZ;
    float s = 0.f;
    for (int i = threadIdx.x; i < HWSZ; i += 256) {
        float v = src[i];
        s = fmaf(v, v, s);
    }
#pragma unroll
    for (int off = 16; off > 0; off >>= 1)
        s += __shfl_xor_sync(0xffffffffu, s, off);
    __shared__ float sm[8];
    int lane = threadIdx.x & 31, wid = threadIdx.x >> 5;
    if (lane == 0) sm[wid] = s;
    __syncthreads();
    if (threadIdx.x < 8) {
        s = sm[threadIdx.x];
#pragma unroll
        for (int off = 4; off > 0; off >>= 1)
            s += __shfl_xor_sync(0xffu, s, off);
        if (threadIdx.x == 0)
            norms[blockIdx.y * (BB * CC) + row] = sqrtf(s);
    }
}

// ---------------- gram partials -------------------------------------------------
__global__ void gram_kernel(const float* __restrict__ q,
                            const float* __restrict__ k,
                            float* __restrict__ part)
{
    __shared__ float qs[24 * 129];
    __shared__ float ksm[24 * 129];

    int bh = blockIdx.x;
    int ks = blockIdx.y;
    int b = bh >> 3, h = bh & 7;
    const float* qb = q + (size_t)b * CC * HWSZ + (size_t)(h * DH) * HWSZ;
    const float* kb = k + (size_t)b * CC * HWSZ + (size_t)(h * DH) * HWSZ;

    int tid = threadIdx.x;
    int d  = tid % 24;
    int c0 = tid / 24;

    float a0 = 0.f, a1 = 0.f, a2 = 0.f;
    int kstart = ks * (HWSZ / NSPLIT);

    for (int kc = kstart; kc < kstart + (HWSZ / NSPLIT); kc += GRAM_TK) {
#pragma unroll
        for (int i = tid; i < 24 * GRAM_TK; i += 192) {
            int r = i / GRAM_TK, cl = i % GRAM_TK;
            qs[r * 129 + cl]  = qb[(size_t)r * HWSZ + kc + cl];
            ksm[r * 129 + cl] = kb[(size_t)r * HWSZ + kc + cl];
        }
        __syncthreads();
#pragma unroll 4
        for (int j = 0; j < GRAM_TK; j++) {
            float kv = ksm[d * 129 + j];
            a0 = fmaf(qs[c0 * 129 + j],        kv, a0);
            a1 = fmaf(qs[(c0 + 8) * 129 + j],  kv, a1);
            a2 = fmaf(qs[(c0 + 16) * 129 + j], kv, a2);
        }
        __syncthreads();
    }
    float* p = part + ((size_t)ks * 64 + bh) * 576;
    p[c0 * 24 + d]        = a0;
    p[(c0 + 8) * 24 + d]  = a1;
    p[(c0 + 16) * 24 + d] = a2;
}

// ---------------- reduce + scale + softmax --------------------------------------
__global__ void softmax_kernel(const float* __restrict__ temp,
                               const float* __restrict__ part,
                               const float* __restrict__ norms,
                               float* __restrict__ attn)
{
    int bh = blockIdx.x;
    int b = bh >> 3, h = bh & 7;
    int r = threadIdx.x;
    if (r >= 24) return;
    float t = temp[h];
    float nq = fmaxf(norms[b * CC + h * DH + r], 1e-12f);
    float l[24];
    float mx = -1e30f;
#pragma unroll
    for (int d = 0; d < 24; d++) {
        float s = 0.f;
        for (int ksp = 0; ksp < NSPLIT; ksp++)
            s += part[((size_t)ksp * 64 + bh) * 576 + r * 24 + d];
        float nk = fmaxf(norms[BB * CC + b * CC + h * DH + d], 1e-12f);
        s = s * t / (nq * nk);
        l[d] = s;
        mx = fmaxf(mx, s);
    }
    float sum = 0.f;
#pragma unroll
    for (int d = 0; d < 24; d++) { l[d] = expf(l[d] - mx); sum += l[d]; }
    float inv = 1.f / sum;
#pragma unroll
    for (int d = 0; d < 24; d++)
        attn[(size_t)bh * 576 + r * 24 + d] = l[d] * inv;
}

// ---------------- attn @ v -------------------------------------------------------
__global__ void av_kernel(const float* __restrict__ attn,
                          const float* __restrict__ v,
                          float* __restrict__ out)
{
    __shared__ float at[576];
    int bh = blockIdx.y;
    int b = bh >> 3, h = bh & 7;
    int tid = threadIdx.x;
    for (int i = tid; i < 576; i += 256) at[i] = attn[(size_t)bh * 576 + i];
    __syncthreads();

    int n = blockIdx.x * 256 + tid;
    size_t base = (size_t)b * CC * HWSZ + (size_t)(h * DH) * HWSZ + n;
    float vv[24];
#pragma unroll
    for (int d = 0; d < 24; d++) vv[d] = v[base + (size_t)d * HWSZ];
#pragma unroll
    for (int c = 0; c < 24; c++) {
        float s = 0.f;
#pragma unroll
        for (int d = 0; d < 24; d++) s = fmaf(at[c * 24 + d], vv[d], s);
        out[base + (size_t)c * HWSZ] = s;
    }
}

// ------------------------------- launcher ----------------------------------------
extern "C" void kernel_launch(void* const* d_in, const int* in_sizes, int n_in,
                              void* d_out, int out_size)
{
    const float* image = (const float*)d_in[0];
    const float* mask  = (const float*)d_in[1];
    const float* n1w   = (const float*)d_in[2];
    const float* n1b   = (const float*)d_in[3];
    const float* Wq    = (const float*)d_in[4];
    const float* Wk    = (const float*)d_in[5];
    const float* Wv    = (const float*)d_in[6];
    const float* Wo    = (const float*)d_in[7];
    const float* temp  = (const float*)d_in[8];
    const float* n2w   = (const float*)d_in[9];
    const float* n2b   = (const float*)d_in[10];
    const float* fc1w  = (const float*)d_in[11];
    const float* fc1b  = (const float*)d_in[12];
    const float* fc2w  = (const float*)d_in[13];
    const float* fc2b  = (const float*)d_in[14];
    float* out = (float*)d_out;

    float *xn, *xm, *q, *k, *v, *oat, *fused, *xln, *hmid, *attn, *part, *norms;
    cudaGetSymbolAddress((void**)&xn,    g_xn);
    cudaGetSymbolAddress((void**)&xm,    g_xm);
    cudaGetSymbolAddress((void**)&q,     g_q);
    cudaGetSymbolAddress((void**)&k,     g_k);
    cudaGetSymbolAddress((void**)&v,     g_v);
    cudaGetSymbolAddress((void**)&oat,   g_oat);
    cudaGetSymbolAddress((void**)&fused, g_fused);
    cudaGetSymbolAddress((void**)&xln,   g_xln);
    cudaGetSymbolAddress((void**)&hmid,  g_hmid);
    cudaGetSymbolAddress((void**)&attn,  g_attn);
    cudaGetSymbolAddress((void**)&part,  g_part);
    cudaGetSymbolAddress((void**)&norms, g_norms);

    dim3 g192(HWSZ / 128, CC / 64, BB);    // (128, 3, 8)
    dim3 g384(HWSZ / 128, HID / 64, BB);   // (128, 6, 8)

    ln_kernel<<<NPIX / 256, 256>>>(image, mask, n1w, n1b, xn, xm);
    sgemm_kernel<false><<<g192, 128>>>(Wq, xm, q, nullptr, nullptr, CC, CC);
    sgemm_kernel<false><<<g192, 128>>>(Wk, xn, k, nullptr, nullptr, CC, CC);
    sgemm_kernel<false><<<g192, 128>>>(Wv, xn, v, nullptr, nullptr, CC, CC);
    rownorm_kernel<<<dim3(BB * CC, 2), 256>>>(q, k, norms);
    gram_kernel<<<dim3(64, NSPLIT), 192>>>(q, k, part);
    softmax_kernel<<<64, 32>>>(temp, part, norms, attn);
    av_kernel<<<dim3(HWSZ / 256, 64), 256>>>(attn, v, oat);
    sgemm_kernel<false><<<g192, 128>>>(Wo, oat, fused, nullptr, image, CC, CC);
    ln_kernel<<<NPIX / 256, 256>>>(fused, nullptr, n2w, n2b, xln, nullptr);
    sgemm_kernel<true><<<g384, 128>>>(fc1w, xln, hmid, fc1b, nullptr, HID, CC);
    sgemm_kernel<false><<<g192, 128>>>(fc2w, hmid, out, fc2b, fused, CC, HID);
}